// round 3
// baseline (speedup 1.0000x reference)
#include <cuda_runtime.h>

// InteractionLayer: per-batch Gram matrix upper triangle.
//   x   : [4096, 64, 128] fp32
//   out : [4096, 2016]    fp32   (strictly upper triangle, row-major i<j)
//
// Strategy (round 1 algorithm; round 3 adds a guarded fallback for the
// packed-FMA asm so a pre-8.6 ptxas cannot kill the device compile):
//   - 1 CTA per batch, 128 threads (4 warps).
//   - X[b] (32 KB) staged in shared memory, no padding (stride 128 floats).
//   - Each of the 64 logical tiles (8x8 thread grid) computes an 8x8 block of
//     the full 64x64 Gram matrix; k is split in half across thread pairs
//     (t, t+64), partials reduced through shared memory.
//   - Accumulation uses packed fma.rn.f32x2 over k-pairs (full-rate FP32 on
//     Blackwell; plain FFMA is half rate). Operands are loaded as 8-byte
//     values straight from smem, so no packing instructions are needed.
//   - Per-lane k rotation (kk0 = 2*lane) makes every 64-bit shared load
//     bank-conflict-free despite the power-of-two row stride.

typedef unsigned long long u64;

#define F      64
#define D      128
#define NPAIR  2016

__device__ __forceinline__ u64 ffma2(u64 a, u64 b, u64 c) {
#if defined(__CUDA_ARCH__) && (__CUDA_ARCH__ >= 1000)
    u64 d;
    asm("fma.rn.f32x2 %0, %1, %2, %3;" : "=l"(d) : "l"(a), "l"(b), "l"(c));
    return d;
#else
    float2 af = *(const float2*)&a, bf = *(const float2*)&b, cf = *(const float2*)&c;
    float2 df;
    df.x = fmaf(af.x, bf.x, cf.x);
    df.y = fmaf(af.y, bf.y, cf.y);
    u64 d; *(float2*)&d = df;
    return d;
#endif
}

__global__ void __launch_bounds__(128)
gram_upper_kernel(const float* __restrict__ x, float* __restrict__ out) {
    __shared__ float sx[F * D];   // 32 KB: X[b], row-major [64][128]

    const int tid = threadIdx.x;
    const int b   = blockIdx.x;

    // ---- stage X[b] into smem: 2048 float4, 16 per thread, fully coalesced
    {
        const float4* g4 = (const float4*)(x + (size_t)b * (F * D));
        float4* s4 = (float4*)sx;
        #pragma unroll
        for (int i = 0; i < 16; ++i)
            s4[tid + i * 128] = g4[tid + i * 128];
    }
    __syncthreads();

    // ---- tile assignment: u = tile id (8x8 grid of 8x8 tiles), k half split
    const int u     = tid & 63;
    const int r0    = (u >> 3) << 3;     // tile rows   [r0, r0+8)
    const int c0    = (u & 7) << 3;      // tile cols   [c0, c0+8)
    const int kbase = (tid >> 6) << 6;   // 0 or 64: this thread's k half

    u64 acc[8][8];
    #pragma unroll
    for (int i = 0; i < 8; ++i)
        #pragma unroll
        for (int j = 0; j < 8; ++j) acc[i][j] = 0ULL;

    // per-lane k rotation: bank = kk mod 32 is distinct within each half-warp
    int kk = (tid * 2) & 63;

    #pragma unroll 4
    for (int it = 0; it < 32; ++it) {
        const float* pk = sx + kbase + kk;
        u64 av[8], bv[8];
        #pragma unroll
        for (int i = 0; i < 8; ++i)
            av[i] = *(const u64*)(pk + (r0 + i) * D);
        #pragma unroll
        for (int j = 0; j < 8; ++j)
            bv[j] = *(const u64*)(pk + (c0 + j) * D);
        #pragma unroll
        for (int i = 0; i < 8; ++i)
            #pragma unroll
            for (int j = 0; j < 8; ++j)
                acc[i][j] = ffma2(av[i], bv[j], acc[i][j]);
        kk = (kk + 2) & 63;
    }

    // ---- horizontal combine of the f32x2 lanes
    float p[64];
    #pragma unroll
    for (int i = 0; i < 8; ++i)
        #pragma unroll
        for (int j = 0; j < 8; ++j) {
            u64 v = acc[i][j];
            p[i * 8 + j] = __uint_as_float((unsigned)v) +
                           __uint_as_float((unsigned)(v >> 32));
        }

    // ---- cross-k-half reduction through smem (reuse sx; stride 65 = no conflicts)
    __syncthreads();   // everyone is done reading sx
    float* red = sx;
    if (tid >= 64) {
        #pragma unroll
        for (int q = 0; q < 64; ++q)
            red[u * 65 + q] = p[q];
    }
    __syncthreads();

    if (tid < 64) {
        float* outb = out + (size_t)b * NPAIR;
        #pragma unroll
        for (int i = 0; i < 8; ++i) {
            const int row  = r0 + i;
            // linear index of (row, col), col>row:  row*(125-row)/2 + col - 1
            const int base = row * (125 - row) / 2 - 1;
            #pragma unroll
            for (int j = 0; j < 8; ++j) {
                const int col = c0 + j;
                if (col > row)
                    outb[base + col] = p[i * 8 + j] + red[u * 65 + i * 8 + j];
            }
        }
    }
}

extern "C" void kernel_launch(void* const* d_in, const int* in_sizes, int n_in,
                              void* d_out, int out_size) {
    const float* x = (const float*)d_in[0];
    float* out = (float*)d_out;
    gram_upper_kernel<<<4096, 128>>>(x, out);
}